// round 6
// baseline (speedup 1.0000x reference)
#include <cuda_runtime.h>
#include <math.h>

#define HID 512
#define QD 32
#define OFFN 496
#define NB 148
#define NT 512
#define NWARP 16

// ---------------- scratch (device globals) ----------------------------------
__device__ float d_h1[HID], d_g1[HID], d_h2[HID], d_g2[HID], d_h3[HID];
__device__ float d_A1[HID * QD];     // diag(s1) W1                [512,32]
__device__ float d_M1[HID * QD];     // diag(s2) W2 A1             [512,32]
__device__ float d_M2[HID * QD];     // diag(s3) W3 M1             [512,32]
__device__ float d_Bo[QD * HID];     // Bo[a,c] = sum_{i>a} qt[i] Wo[p(i,a),c]
__device__ float d_wvec[HID];        // w = M2 @ q_t               [512]
__device__ float d_v[QD + OFFN];     // v = dh4 @ w                [528]
__device__ float d_F[QD * QD];       // F = Beff @ M2              [32,32]
__device__ float d_ldiag[QD], d_loff[OFFN], d_gvec[QD];

// ---------------- hierarchical grid barrier ----------------------------------
// Arrive: atomicAdd on one of 8 group counters (each on its own 128B line,
// <=19 arrivals each, parallel across L2 slices). Last group arriver resets its
// counter (atomicExch) and bumps the root; last root arriver resets root and
// releases via the volatile generation word (round-3-proven mechanism).
__device__ unsigned int g_cnt[8 * 32];   // counter g at g_cnt[g*32]
__device__ unsigned int g_root = 0;
__device__ volatile unsigned int g_gen = 0;

__device__ __forceinline__ void barrier_arrive_core(int b) {
    int gi = b & 7;
    unsigned int gsz = 18u + (gi < 4 ? 1u : 0u);   // 148 = 4*19 + 4*18
    if (atomicAdd(&g_cnt[gi * 32], 1u) == gsz - 1u) {
        atomicExch(&g_cnt[gi * 32], 0u);           // reset before root bump
        if (atomicAdd(&g_root, 1u) == 7u) {
            atomicExch(&g_root, 0u);
            __threadfence();
            g_gen = g_gen + 1u;
        }
    }
}

__device__ __forceinline__ void grid_arrive() {
    __syncthreads();
    __threadfence();
    if (threadIdx.x == 0) barrier_arrive_core(blockIdx.x);
}

__device__ __forceinline__ void grid_sync() {
    __syncthreads();
    __threadfence();
    if (threadIdx.x == 0) {
        unsigned int gen = g_gen;
        barrier_arrive_core(blockIdx.x);
        while (g_gen == gen) { }
    }
    __syncthreads();
}

__device__ __forceinline__ float sigm(float x) { return 1.f / (1.f + expf(-x)); }

// warp dot of length 512; W read-only path, x coherent. Result in all lanes.
__device__ __forceinline__ float wdot512(const float* __restrict__ W,
                                         const float* __restrict__ x, int lane) {
    const float4* W4 = (const float4*)W;
    const float4* x4 = (const float4*)x;
    float4 wa = __ldg(W4 + lane);      float4 xa = x4[lane];
    float4 wb = __ldg(W4 + lane + 32); float4 xb = x4[lane + 32];
    float4 wc = __ldg(W4 + lane + 64); float4 xc = x4[lane + 64];
    float4 wd = __ldg(W4 + lane + 96); float4 xd = x4[lane + 96];
    float a0 = wa.x * xa.x + wa.y * xa.y + wa.z * xa.z + wa.w * xa.w;
    float a1 = wb.x * xb.x + wb.y * xb.y + wb.z * xb.z + wb.w * xb.w;
    float a2 = wc.x * xc.x + wc.y * xc.y + wc.z * xc.z + wc.w * xc.w;
    float a3 = wd.x * xd.x + wd.y * xd.y + wd.z * xd.z + wd.w * xd.w;
    float acc = (a0 + a1) + (a2 + a3);
#pragma unroll
    for (int o = 16; o; o >>= 1) acc += __shfl_xor_sync(0xffffffffu, acc, o);
    return acc;
}

// GEMM core after sw[] is staged with 4 rows (4*512 floats).
__device__ __forceinline__ void gemm4_core(int rbase,
                                           const float* __restrict__ M,
                                           const float* __restrict__ hvec,
                                           float* __restrict__ Y,
                                           const float* __restrict__ qt,
                                           float* __restrict__ wvec_out,
                                           const float* __restrict__ sw,
                                           float* __restrict__ sp) {
    int tid = threadIdx.x;
    int lane = tid & 31, w = tid >> 5;
    const float4* sw4 = (const float4*)sw;
    float a0 = 0.f, a1 = 0.f, a2 = 0.f, a3 = 0.f;
#pragma unroll
    for (int t = 0; t < 8; t++) {
        int c4 = w * 8 + t;
        int c = c4 * 4;
        float m0 = M[(c + 0) * QD + lane];
        float m1 = M[(c + 1) * QD + lane];
        float m2 = M[(c + 2) * QD + lane];
        float m3 = M[(c + 3) * QD + lane];
        float4 v0 = sw4[c4];
        float4 v1 = sw4[128 + c4];
        float4 v2 = sw4[256 + c4];
        float4 v3 = sw4[384 + c4];
        a0 += v0.x * m0 + v0.y * m1 + v0.z * m2 + v0.w * m3;
        a1 += v1.x * m0 + v1.y * m1 + v1.z * m2 + v1.w * m3;
        a2 += v2.x * m0 + v2.y * m1 + v2.z * m2 + v2.w * m3;
        a3 += v3.x * m0 + v3.y * m1 + v3.z * m2 + v3.w * m3;
    }
    sp[(w * 4 + 0) * 33 + lane] = a0;
    sp[(w * 4 + 1) * 33 + lane] = a1;
    sp[(w * 4 + 2) * 33 + lane] = a2;
    sp[(w * 4 + 3) * 33 + lane] = a3;
    __syncthreads();
    if (tid < 128) {
        int i = tid >> 5, j = lane;
        float s = 0.f;
#pragma unroll
        for (int u = 0; u < 16; u++) s += sp[(u * 4 + i) * 33 + j];
        int r = rbase + i;
        float val = s;
        if (hvec) {
            float h = hvec[r];
            val = h * (1.f - h) * s;
        }
        Y[r * QD + j] = val;
        if (wvec_out) {
            float contrib = val * __ldg(qt + j);
#pragma unroll
            for (int o = 16; o; o >>= 1)
                contrib += __shfl_xor_sync(0xffffffffu, contrib, o);
            if (j == 0) wvec_out[r] = contrib;
        }
    }
    __syncthreads();
}

// ---------------- the one kernel ---------------------------------------------
__global__ __launch_bounds__(NT)
void fused(const float* __restrict__ q, const float* __restrict__ q_t,
           const float* __restrict__ q_tt,
           const float* __restrict__ W1, const float* __restrict__ b1,
           const float* __restrict__ W2, const float* __restrict__ b2,
           const float* __restrict__ W3, const float* __restrict__ b3,
           const float* __restrict__ Wd, const float* __restrict__ bd,
           const float* __restrict__ Wo, const float* __restrict__ bo,
           const float* __restrict__ Wg1, const float* __restrict__ bg1,
           const float* __restrict__ Wg2, const float* __restrict__ bg2,
           const float* __restrict__ Wg3, const float* __restrict__ bg3,
           float* __restrict__ out) {
    __shared__ float shm[4288];   // sw[2048] | sp[2112] | misc[128]
    int b = blockIdx.x, tid = threadIdx.x;
    int lane = tid & 31, w = tid >> 5;

    // ======== S1: Bo (32 blocks), h1 (1 block), g1 (1 block) ================
    if (b < 32) {
        int t = b * NT + tid;                   // 0..16383
        int a = t >> 9, c = t & 511;
        float acc = 0.f;
#pragma unroll
        for (int i = 1; i < 32; i++) {
            if (i > a)
                acc += __ldg(q_t + i) *
                       __ldg(Wo + (((i * (i - 1)) >> 1) + a) * HID + c);
        }
        d_Bo[t] = acc;
    } else if (b == 32) {
        int r = tid;                            // 0..511
        float acc = __ldg(b1 + r);
        const float4* w4 = (const float4*)(W1 + r * QD);
        const float4* q4 = (const float4*)q;
#pragma unroll
        for (int k = 0; k < 8; k++) {
            float4 a = __ldg(w4 + k), bb = __ldg(q4 + k);
            acc += a.x * bb.x + a.y * bb.y + a.z * bb.z + a.w * bb.w;
        }
        d_h1[r] = sigm(acc);
    } else if (b == 33) {
        int r = tid;
        float acc = __ldg(bg1 + r);
        const float4* w4 = (const float4*)(Wg1 + r * QD);
        const float4* q4 = (const float4*)q;
#pragma unroll
        for (int k = 0; k < 8; k++) {
            float4 a = __ldg(w4 + k), bb = __ldg(q4 + k);
            acc += a.x * bb.x + a.y * bb.y + a.z * bb.z + a.w * bb.w;
        }
        d_g1[r] = sigm(acc);
    }
    grid_sync();

    // ======== S2: h2 (32 blk), g2 (32 blk), A1 (8 blk) ======================
    if (b < 32) {
        int r = b * NWARP + w;                  // 0..511
        float acc = wdot512(W2 + r * HID, d_h1, lane);
        if (lane == 0) d_h2[r] = sigm(acc + __ldg(b2 + r));
    } else if (b < 64) {
        int r = (b - 32) * NWARP + w;
        float acc = wdot512(Wg2 + r * HID, d_g1, lane);
        if (lane == 0) d_g2[r] = sigm(acc + __ldg(bg2 + r));
    } else if (b < 72) {
        int t4 = (b - 64) * NT + tid;           // 0..4095
        float4 wv = __ldg(((const float4*)W1) + t4);
        float h = d_h1[t4 >> 3];
        float s = h * (1.f - h);
        ((float4*)d_A1)[t4] = make_float4(s * wv.x, s * wv.y, s * wv.z, s * wv.w);
    }
    grid_sync();

    // ======== S3: M1 = diag(s2) W2 A1 (128 blk) ; h3 (20 blk) ===============
    if (b < 128) {
        int rbase = b * 4;
        ((float4*)shm)[tid] = __ldg((const float4*)(W2 + rbase * HID) + tid);
        __syncthreads();
        gemm4_core(rbase, d_A1, d_h2, d_M1, nullptr, nullptr, shm, shm + 2048);
    } else {
        for (int r = (b - 128) * NWARP + w; r < HID; r += 20 * NWARP) {
            float acc = wdot512(W3 + r * HID, d_h2, lane);
            if (lane == 0) d_h3[r] = sigm(acc + __ldg(b3 + r));
        }
    }
    grid_sync();

    // ======== S4: M2 (+wvec) (128 blk) ; loff/ldiag/gvec (20 blk) ===========
    if (b < 128) {
        int rbase = b * 4;
        ((float4*)shm)[tid] = __ldg((const float4*)(W3 + rbase * HID) + tid);
        __syncthreads();
        gemm4_core(rbase, d_M1, d_h3, d_M2, q_t, d_wvec, shm, shm + 2048);
    } else {
        for (int tk = (b - 128) * NWARP + w; tk < OFFN + 2 * QD; tk += 20 * NWARP) {
            if (tk < OFFN) {
                float acc = wdot512(Wo + tk * HID, d_h3, lane);
                if (lane == 0) d_loff[tk] = acc + __ldg(bo + tk);
            } else if (tk < OFFN + QD) {
                int i = tk - OFFN;
                float acc = wdot512(Wd + i * HID, d_h3, lane);
                if (lane == 0) d_ldiag[i] = expf(acc + __ldg(bd + i));
            } else {
                int i = tk - OFFN - QD;
                float acc = wdot512(Wg3 + i * HID, d_g2, lane);
                if (lane == 0) d_gvec[i] = acc + __ldg(bg3 + i);
            }
        }
    }
    grid_sync();

    // ======== S5: F = Beff @ M2 (8 blk) ; v = dh4 @ w (33 blk) ==============
    if (b < 8) {
        int rbase = b * 4;
        if (tid < 4)
            shm[4160 + tid] = __ldg(q_t + rbase + tid) * d_ldiag[rbase + tid];
        __syncthreads();
        int row = tid >> 7, c4l = tid & 127;
        float ql = shm[4160 + row];
        float4 wv = __ldg((const float4*)(Wd + (rbase + row) * HID) + c4l);
        float4 bv = ((const float4*)(d_Bo + (rbase + row) * HID))[c4l];
        ((float4*)shm)[tid] = make_float4(ql * wv.x + bv.x, ql * wv.y + bv.y,
                                          ql * wv.z + bv.z, ql * wv.w + bv.w);
        __syncthreads();
        gemm4_core(rbase, d_M2, nullptr, d_F, nullptr, nullptr, shm, shm + 2048);
    } else if (b < 41) {
        int r = (b - 8) * NWARP + w;            // 0..527
        if (r < QD) {
            float acc = wdot512(Wd + r * HID, d_wvec, lane);
            if (lane == 0) d_v[r] = d_ldiag[r] * acc;
        } else {
            int p = r - QD;
            float acc = wdot512(Wo + p * HID, d_wvec, lane);
            if (lane == 0) d_v[r] = acc;
        }
    }
    // last barrier: only block 0 consumes S5 outputs; others arrive and exit
    if (b != 0) {
        grid_arrive();
        return;
    }
    grid_sync();

    // ======== S6: final assembly (block 0 only) =============================
    // tau = c1 + c2 + 0.5*c3 - 0.5*c4 + g   (comp_5 == comp_3)
    {
        float* sL = shm;            // [32][33]
        float* sD = shm + 1056;     // [32][33]
        float* sm = shm + 2112;
        float* sqt = sm, *sqtt = sm + 32, *sLTqt = sm + 64,
             * su1 = sm + 96, *su2 = sm + 128;
        if (tid < QD) { sqt[tid] = __ldg(q_t + tid); sqtt[tid] = __ldg(q_tt + tid); }
        __syncthreads();
        for (int t = tid; t < QD * QD; t += NT) {
            int i = t >> 5, j = t & 31;
            float lv = 0.f, dv = 0.f;
            if (i == j) { lv = d_ldiag[i]; dv = d_v[i]; }
            else if (i > j) {
                int p = ((i * (i - 1)) >> 1) + j;
                lv = d_loff[p]; dv = d_v[QD + p];
            }
            sL[i * 33 + j] = lv; sD[i * 33 + j] = dv;
        }
        __syncthreads();
        if (tid < QD) {
            int j = tid;
            float a = 0.f, bb = 0.f, c = 0.f;
#pragma unroll
            for (int i = 0; i < QD; i++) {
                a  += sL[i * 33 + j] * sqt[i];
                bb += sL[i * 33 + j] * sqtt[i];
                c  += sD[i * 33 + j] * sqt[i];
            }
            sLTqt[j] = a; su1[j] = bb; su2[j] = c;
        }
        __syncthreads();
        if (tid < QD) {
            int i = tid;
            float acc = d_gvec[i];
#pragma unroll
            for (int j = 0; j < QD; j++) {
                acc += sL[i * 33 + j] * (su1[j] + su2[j]) +
                       0.5f * (sD[i * 33 + j] - d_F[i * QD + j]) * sLTqt[j];
            }
            out[i] = acc;
        }
    }
}

// ---------------- launch ------------------------------------------------------
extern "C" void kernel_launch(void* const* d_in, const int* in_sizes, int n_in,
                              void* d_out, int out_size) {
    const float* q    = (const float*)d_in[0];
    const float* q_t  = (const float*)d_in[1];
    const float* q_tt = (const float*)d_in[2];
    const float* W1   = (const float*)d_in[3];
    const float* b1   = (const float*)d_in[4];
    const float* W2   = (const float*)d_in[5];
    const float* b2   = (const float*)d_in[6];
    const float* W3   = (const float*)d_in[7];
    const float* b3   = (const float*)d_in[8];
    const float* Wd   = (const float*)d_in[9];
    const float* bd   = (const float*)d_in[10];
    const float* Wo   = (const float*)d_in[11];
    const float* bo   = (const float*)d_in[12];
    const float* Wg1  = (const float*)d_in[13];
    const float* bg1  = (const float*)d_in[14];
    const float* Wg2  = (const float*)d_in[15];
    const float* bg2  = (const float*)d_in[16];
    const float* Wg3  = (const float*)d_in[17];
    const float* bg3  = (const float*)d_in[18];
    float* out = (float*)d_out;

    fused<<<NB, NT>>>(q, q_t, q_tt, W1, b1, W2, b2, W3, b3, Wd, bd, Wo, bo,
                      Wg1, bg1, Wg2, bg2, Wg3, bg3, out);
}

// round 7
// speedup vs baseline: 1.0643x; 1.0643x over previous
#include <cuda_runtime.h>
#include <math.h>

#define HID 512
#define QD 32
#define OFFN 496
#define NB 148
#define NT 512
#define NWARP 16

// ---------------- scratch (device globals) ----------------------------------
__device__ float d_h2[HID], d_g2[HID], d_h3[HID];
__device__ float d_A1[HID * QD];     // diag(s1) W1                 [512,32]
__device__ float d_M1[HID * QD];     // diag(s2) W2 A1              [512,32]
__device__ float d_M2[HID * QD];     // diag(s3) W3 M1              [512,32]
__device__ float d_wvec[HID];        // w = M2 @ q_t                [512]
__device__ float d_ldiag[QD], d_loff[OFFN], d_gvec[QD];
__device__ float d_zow[OFFN], d_zoy[OFFN];  // Wo@w, Wo@y
__device__ float d_zdw[QD],  d_zdy[QD];     // Wd@w, Wd@y

// ---------------- flat grid barrier (R4-proven) ------------------------------
__device__ unsigned int g_arrive[2] = {0u, 0u};
__device__ volatile unsigned int g_gen[2] = {0u, 0u};

__device__ __forceinline__ void grid_sync(int id, unsigned int count) {
    __syncthreads();
    __threadfence();
    if (threadIdx.x == 0) {
        unsigned int gen = g_gen[id];
        if (atomicAdd(&g_arrive[id], 1u) == count - 1u) {
            g_arrive[id] = 0u;
            __threadfence();
            g_gen[id] = gen + 1u;
        } else {
            while (g_gen[id] == gen) { }
        }
    }
    __syncthreads();
}

__device__ __forceinline__ void grid_arrive(int id, unsigned int count) {
    __syncthreads();
    __threadfence();
    if (threadIdx.x == 0) {
        unsigned int gen = g_gen[id];
        if (atomicAdd(&g_arrive[id], 1u) == count - 1u) {
            g_arrive[id] = 0u;
            __threadfence();
            g_gen[id] = gen + 1u;
        }
    }
}

__device__ __forceinline__ float sigm(float x) { return 1.f / (1.f + expf(-x)); }

// warp dot length-512: W read-only, x global coherent. Result in all lanes.
__device__ __forceinline__ float wdot512(const float* __restrict__ W,
                                         const float* __restrict__ x, int lane) {
    const float4* W4 = (const float4*)W;
    const float4* x4 = (const float4*)x;
    float acc = 0.f;
#pragma unroll
    for (int k = 0; k < 4; k++) {
        int idx = lane + 32 * k;
        float4 a = __ldg(W4 + idx);
        float4 b = x4[idx];
        acc += a.x * b.x + a.y * b.y + a.z * b.z + a.w * b.w;
    }
#pragma unroll
    for (int o = 16; o; o >>= 1) acc += __shfl_xor_sync(0xffffffffu, acc, o);
    return acc;
}

// warp dot length-512 with x in shared memory.
__device__ __forceinline__ float wdot512_sx(const float* __restrict__ W,
                                            const float* __restrict__ xs, int lane) {
    const float4* W4 = (const float4*)W;
    const float4* x4 = (const float4*)xs;
    float acc = 0.f;
#pragma unroll
    for (int k = 0; k < 4; k++) {
        int idx = lane + 32 * k;
        float4 a = __ldg(W4 + idx);
        float4 b = x4[idx];
        acc += a.x * b.x + a.y * b.y + a.z * b.z + a.w * b.w;
    }
#pragma unroll
    for (int o = 16; o; o >>= 1) acc += __shfl_xor_sync(0xffffffffu, acc, o);
    return acc;
}

// per-thread length-32 dot of a W-row block vs q (8 float4 each)
__device__ __forceinline__ float dot32(const float* __restrict__ Wrow,
                                       const float* __restrict__ q, float bias) {
    const float4* w4 = (const float4*)Wrow;
    const float4* q4 = (const float4*)q;
    float acc = bias;
#pragma unroll
    for (int k = 0; k < 8; k++) {
        float4 a = __ldg(w4 + k), b = __ldg(q4 + k);
        acc += a.x * b.x + a.y * b.y + a.z * b.z + a.w * b.w;
    }
    return acc;
}

// GEMM core after sw[] staged with 4 rows (4*512 floats).
__device__ __forceinline__ void gemm4_core(int rbase,
                                           const float* __restrict__ M,
                                           const float* __restrict__ hvec,
                                           float* __restrict__ Y,
                                           const float* __restrict__ qt,
                                           float* __restrict__ wvec_out,
                                           const float* __restrict__ sw,
                                           float* __restrict__ sp) {
    int tid = threadIdx.x;
    int lane = tid & 31, w = tid >> 5;
    const float4* sw4 = (const float4*)sw;
    float a0 = 0.f, a1 = 0.f, a2 = 0.f, a3 = 0.f;
#pragma unroll
    for (int t = 0; t < 8; t++) {
        int c4 = w * 8 + t;
        int c = c4 * 4;
        float m0 = M[(c + 0) * QD + lane];
        float m1 = M[(c + 1) * QD + lane];
        float m2 = M[(c + 2) * QD + lane];
        float m3 = M[(c + 3) * QD + lane];
        float4 v0 = sw4[c4];
        float4 v1 = sw4[128 + c4];
        float4 v2 = sw4[256 + c4];
        float4 v3 = sw4[384 + c4];
        a0 += v0.x * m0 + v0.y * m1 + v0.z * m2 + v0.w * m3;
        a1 += v1.x * m0 + v1.y * m1 + v1.z * m2 + v1.w * m3;
        a2 += v2.x * m0 + v2.y * m1 + v2.z * m2 + v2.w * m3;
        a3 += v3.x * m0 + v3.y * m1 + v3.z * m2 + v3.w * m3;
    }
    sp[(w * 4 + 0) * 33 + lane] = a0;
    sp[(w * 4 + 1) * 33 + lane] = a1;
    sp[(w * 4 + 2) * 33 + lane] = a2;
    sp[(w * 4 + 3) * 33 + lane] = a3;
    __syncthreads();
    if (tid < 128) {
        int i = tid >> 5, j = lane;
        float s = 0.f;
#pragma unroll
        for (int u = 0; u < 16; u++) s += sp[(u * 4 + i) * 33 + j];
        int r = rbase + i;
        float val = s;
        if (hvec) {
            float h = hvec[r];
            val = h * (1.f - h) * s;
        }
        Y[r * QD + j] = val;
        if (wvec_out) {
            float contrib = val * __ldg(qt + j);
#pragma unroll
            for (int o = 16; o; o >>= 1)
                contrib += __shfl_xor_sync(0xffffffffu, contrib, o);
            if (j == 0) wvec_out[r] = contrib;
        }
    }
    __syncthreads();
}

// ---------------- the one kernel ---------------------------------------------
__global__ __launch_bounds__(NT)
void fused(const float* __restrict__ q, const float* __restrict__ q_t,
           const float* __restrict__ q_tt,
           const float* __restrict__ W1, const float* __restrict__ b1,
           const float* __restrict__ W2, const float* __restrict__ b2,
           const float* __restrict__ W3, const float* __restrict__ b3,
           const float* __restrict__ Wd, const float* __restrict__ bd,
           const float* __restrict__ Wo, const float* __restrict__ bo,
           const float* __restrict__ Wg1, const float* __restrict__ bg1,
           const float* __restrict__ Wg2, const float* __restrict__ bg2,
           const float* __restrict__ Wg3, const float* __restrict__ bg3,
           float* __restrict__ out) {
    __shared__ float shm[4288];   // sw[2048] | sp[2112] | misc
    int b = blockIdx.x, tid = threadIdx.x;
    int lane = tid & 31, w = tid >> 5;

    // ======== Stage A: h1(redundant)->h2, g1(redundant)->g2, A1 =============
    if (b < 32) {
        shm[tid] = sigm(dot32(W1 + tid * QD, q, __ldg(b1 + tid)));
        __syncthreads();
        int r = b * NWARP + w;                  // 0..511
        float acc = wdot512_sx(W2 + r * HID, shm, lane);
        if (lane == 0) d_h2[r] = sigm(acc + __ldg(b2 + r));
    } else if (b < 64) {
        shm[tid] = sigm(dot32(Wg1 + tid * QD, q, __ldg(bg1 + tid)));
        __syncthreads();
        int r = (b - 32) * NWARP + w;
        float acc = wdot512_sx(Wg2 + r * HID, shm, lane);
        if (lane == 0) d_g2[r] = sigm(acc + __ldg(bg2 + r));
    } else if (b < 72) {
        int rb = (b - 64) * 64;                 // 64 h1-rows this block covers
        if (tid < 64)
            shm[tid] = sigm(dot32(W1 + (rb + tid) * QD, q, __ldg(b1 + rb + tid)));
        __syncthreads();
        int t4 = (b - 64) * NT + tid;           // float4 index into A1
        float4 wv = __ldg(((const float4*)W1) + t4);
        float h = shm[(t4 >> 3) - rb];
        float s = h * (1.f - h);
        ((float4*)d_A1)[t4] = make_float4(s * wv.x, s * wv.y, s * wv.z, s * wv.w);
    }
    grid_sync(0, NB);

    // ======== Stage B: M1 = diag(s2) W2 A1 (128 blk) ; h3 (20 blk) ==========
    if (b < 128) {
        int rbase = b * 4;
        ((float4*)shm)[tid] = __ldg((const float4*)(W2 + rbase * HID) + tid);
        __syncthreads();
        gemm4_core(rbase, d_A1, d_h2, d_M1, nullptr, nullptr, shm, shm + 2048);
    } else {
        for (int r = (b - 128) * NWARP + w; r < HID; r += 20 * NWARP) {
            float acc = wdot512(W3 + r * HID, d_h2, lane);
            if (lane == 0) d_h3[r] = sigm(acc + __ldg(b3 + r));
        }
    }
    grid_sync(0, NB);

    // ======== Stage C: M2 (+wvec) (128 blk) ; loff/ldiag/gvec (20 blk) ======
    if (b < 128) {
        int rbase = b * 4;
        ((float4*)shm)[tid] = __ldg((const float4*)(W3 + rbase * HID) + tid);
        __syncthreads();
        gemm4_core(rbase, d_M1, d_h3, d_M2, q_t, d_wvec, shm, shm + 2048);
    } else {
        for (int tk = (b - 128) * NWARP + w; tk < OFFN + 2 * QD; tk += 20 * NWARP) {
            if (tk < OFFN) {
                float acc = wdot512(Wo + tk * HID, d_h3, lane);
                if (lane == 0) d_loff[tk] = acc + __ldg(bo + tk);
            } else if (tk < OFFN + QD) {
                int i = tk - OFFN;
                float acc = wdot512(Wd + i * HID, d_h3, lane);
                if (lane == 0) d_ldiag[i] = expf(acc + __ldg(bd + i));
            } else {
                int i = tk - OFFN - QD;
                float acc = wdot512(Wg3 + i * HID, d_g2, lane);
                if (lane == 0) d_gvec[i] = acc + __ldg(bg3 + i);
            }
        }
    }
    // blocks >= 33 are done: arrive at barrier 3 and exit
    if (b >= 33) {
        grid_arrive(0, NB);
        return;
    }
    grid_sync(0, NB);

    // ======== Stage D (blocks 0..32): LTqt, y = M2@LTqt, dual matvecs =======
    {
        float* sLo = shm;           // [496]
        float* sLd = shm + 496;     // [32]
        float* sqt = shm + 528;     // [32]
        float* sLT = shm + 560;     // [32]
        float* sy  = shm + 592;     // [512]
        if (tid < OFFN) sLo[tid] = d_loff[tid];
        if (tid < QD) { sLd[tid] = d_ldiag[tid]; sqt[tid] = __ldg(q_t + tid); }
        __syncthreads();
        if (tid < QD) {
            int j = tid;
            float a = sLd[j] * sqt[j];
            for (int i = j + 1; i < QD; i++)
                a += sLo[((i * (i - 1)) >> 1) + j] * sqt[i];
            sLT[j] = a;
        }
        __syncthreads();
        {   // y_r = M2[r,:] . LTqt   (one row per thread)
            float acc = 0.f;
            const float4* m4 = (const float4*)(d_M2 + tid * QD);
#pragma unroll
            for (int t = 0; t < 8; t++) {
                float4 mv = m4[t];
                acc += mv.x * sLT[4 * t] + mv.y * sLT[4 * t + 1] +
                       mv.z * sLT[4 * t + 2] + mv.w * sLT[4 * t + 3];
            }
            sy[tid] = acc;
        }
        __syncthreads();
        // dual matvec: one warp per row, two RHS (w global, y smem)
        int task = b * NWARP + w;               // 0..527
        const float* Wrow = (task < OFFN) ? (Wo + task * HID)
                                          : (Wd + (task - OFFN) * HID);
        const float4* W4 = (const float4*)Wrow;
        const float4* xw = (const float4*)d_wvec;
        const float4* xy = (const float4*)sy;
        float aw = 0.f, ay = 0.f;
#pragma unroll
        for (int k = 0; k < 4; k++) {
            int idx = lane + 32 * k;
            float4 wv = __ldg(W4 + idx);
            float4 a = xw[idx];
            float4 c = xy[idx];
            aw += wv.x * a.x + wv.y * a.y + wv.z * a.z + wv.w * a.w;
            ay += wv.x * c.x + wv.y * c.y + wv.z * c.z + wv.w * c.w;
        }
#pragma unroll
        for (int o = 16; o; o >>= 1) {
            aw += __shfl_xor_sync(0xffffffffu, aw, o);
            ay += __shfl_xor_sync(0xffffffffu, ay, o);
        }
        if (lane == 0) {
            if (task < OFFN) { d_zow[task] = aw; d_zoy[task] = ay; }
            else { d_zdw[task - OFFN] = aw; d_zdy[task - OFFN] = ay; }
        }
    }
    if (b != 0) {
        grid_arrive(1, 33);
        return;
    }
    grid_sync(1, 33);

    // ======== Final (block 0): tau = c1+c2 + 0.5*c3 - 0.5*c4 + g ============
    {
        float* sLo  = shm;          // [496]
        float* sLd  = shm + 496;    // [32]
        float* szow = shm + 528;    // [496]
        float* szoy = shm + 1024;   // [496]
        float* szdw = shm + 1520;   // [32]
        float* szdy = shm + 1552;   // [32]
        float* sqt  = shm + 1584;   // [32]
        float* sqtt = shm + 1616;   // [32]
        float* sgv  = shm + 1648;   // [32]
        float* sLT  = shm + 1680;   // [32]
        float* st   = shm + 1712;   // [32]
        for (int t = tid; t < OFFN; t += NT) {
            sLo[t] = d_loff[t]; szow[t] = d_zow[t]; szoy[t] = d_zoy[t];
        }
        if (tid < QD) {
            sLd[tid] = d_ldiag[tid]; szdw[tid] = d_zdw[tid]; szdy[tid] = d_zdy[tid];
            sqt[tid] = __ldg(q_t + tid); sqtt[tid] = __ldg(q_tt + tid);
            sgv[tid] = d_gvec[tid];
        }
        __syncthreads();
        if (tid < QD) {
            int j = tid;
            float lt = sLd[j] * sqt[j];
            float u1 = sLd[j] * sqtt[j];
            float s2 = sLd[j] * szdw[j] * sqt[j];     // v_diag_j * qt_j
            for (int i = j + 1; i < QD; i++) {
                int p = ((i * (i - 1)) >> 1) + j;
                lt += sLo[p] * sqt[i];
                u1 += sLo[p] * sqtt[i];
                s2 += szow[p] * sqt[i];
            }
            sLT[j] = lt;
            st[j] = u1 + s2;
        }
        __syncthreads();
        if (tid < QD) {
            int i = tid;
            float c12 = sLd[i] * st[i];
            float c3  = sLd[i] * szdw[i] * sLT[i];
            float c4  = sqt[i] * sLd[i] * szdy[i];
            for (int j = 0; j < i; j++) {
                int p = ((i * (i - 1)) >> 1) + j;
                c12 += sLo[p] * st[j];
                c3  += szow[p] * sLT[j];
            }
            for (int k = i + 1; k < QD; k++) {
                int p = ((k * (k - 1)) >> 1) + i;
                c4 += sqt[k] * szoy[p];
            }
            out[i] = c12 + 0.5f * (c3 - c4) + sgv[i];
        }
    }
}

// ---------------- launch ------------------------------------------------------
extern "C" void kernel_launch(void* const* d_in, const int* in_sizes, int n_in,
                              void* d_out, int out_size) {
    const float* q    = (const float*)d_in[0];
    const float* q_t  = (const float*)d_in[1];
    const float* q_tt = (const float*)d_in[2];
    const float* W1   = (const float*)d_in[3];
    const float* b1   = (const float*)d_in[4];
    const float* W2   = (const float*)d_in[5];
    const float* b2   = (const float*)d_in[6];
    const float* W3   = (const float*)d_in[7];
    const float* b3   = (const float*)d_in[8];
    const float* Wd   = (const float*)d_in[9];
    const float* bd   = (const float*)d_in[10];
    const float* Wo   = (const float*)d_in[11];
    const float* bo   = (const float*)d_in[12];
    const float* Wg1  = (const float*)d_in[13];
    const float* bg1  = (const float*)d_in[14];
    const float* Wg2  = (const float*)d_in[15];
    const float* bg2  = (const float*)d_in[16];
    const float* Wg3  = (const float*)d_in[17];
    const float* bg3  = (const float*)d_in[18];
    float* out = (float*)d_out;

    fused<<<NB, NT>>>(q, q_t, q_tt, W1, b1, W2, b2, W3, b3, Wd, bd, Wo, bo,
                      Wg1, bg1, Wg2, bg2, Wg3, bg3, out);
}